// round 17
// baseline (speedup 1.0000x reference)
#include <cuda_runtime.h>
#include <cuda_fp16.h>
#include <math.h>

#define N_MAX 100000
#define E_MAX 1600000
#define DH 128
#define DOUT 40
#define DOUTP 64
#define BN_EPS 1e-5f
#define SCAN_B 1024
#define NB_MAX 128

// ---------------- scratch ----------------
__device__ int    g_deg[N_MAX];
__device__ int    g_incl[N_MAX];
__device__ int    g_bsum[NB_MAX];
__device__ int    g_rowstart[N_MAX];
__device__ int    g_cursor[N_MAX];
__device__ float  g_disq[N_MAX];
__device__ int2   g_csr[E_MAX];
__device__ __half g_t16[(size_t)N_MAX * DH];
__device__ __half g_t40[(size_t)N_MAX * DOUTP];
__device__ __half g_h16[(size_t)N_MAX * DH];
__device__ float  g_stats0[2 * DH];
__device__ float  g_stats1[2 * DH];

// ---------------- stream/event for graph fork (load-time init, no device alloc) ----
static cudaStream_t g_s2;
static cudaEvent_t  g_ev_fork, g_ev_join;
static struct StreamInit {
    StreamInit() {
        cudaStreamCreateWithFlags(&g_s2, cudaStreamNonBlocking);
        cudaEventCreateWithFlags(&g_ev_fork, cudaEventDisableTiming);
        cudaEventCreateWithFlags(&g_ev_join, cudaEventDisableTiming);
    }
} g_stream_init;

// ---------------- helpers ----------------
__device__ __forceinline__ void red_add_v4(float* p, float4 v) {
    asm volatile("red.global.add.v4.f32 [%0], {%1,%2,%3,%4};"
                 :: "l"(p), "f"(v.x), "f"(v.y), "f"(v.z), "f"(v.w) : "memory");
}
__device__ __forceinline__ void mma_f16(float* d, const unsigned* a, const unsigned* b) {
    asm volatile(
        "mma.sync.aligned.m16n8k16.row.col.f32.f16.f16.f32 "
        "{%0,%1,%2,%3}, {%4,%5,%6,%7}, {%8,%9}, {%0,%1,%2,%3};\n"
        : "+f"(d[0]), "+f"(d[1]), "+f"(d[2]), "+f"(d[3])
        : "r"(a[0]), "r"(a[1]), "r"(a[2]), "r"(a[3]),
          "r"(b[0]), "r"(b[1]));
}
__device__ __forceinline__ void h2x2_to_f4(uint2 u, float4& o) {
    float2 f0 = __half22float2(*(__half2*)&u.x);
    float2 f1 = __half22float2(*(__half2*)&u.y);
    o.x = f0.x; o.y = f0.y; o.z = f1.x; o.w = f1.y;
}
__device__ __forceinline__ uint2 f4_to_h2x2(float4 h) {
    __half2 a = __float22half2_rn(make_float2(h.x, h.y));
    __half2 b = __float22half2_rn(make_float2(h.z, h.w));
    uint2 o;
    o.x = *(unsigned*)&a;
    o.y = *(unsigned*)&b;
    return o;
}
__device__ __forceinline__ unsigned h2u(float a, float b) {
    __half2 h = __float22half2_rn(make_float2(a, b));
    return *(unsigned*)&h;
}

// ---------------- CSR build ----------------
__global__ void zero_misc(int n) {
    int i = blockIdx.x * blockDim.x + threadIdx.x;
    if (i < n) g_deg[i] = 0;
    if (i < 2 * DH) { g_stats0[i] = 0.0f; g_stats1[i] = 0.0f; }
}
__global__ void count_deg(const int* __restrict__ dst, int e) {
    int i = blockIdx.x * blockDim.x + threadIdx.x;
    if (i < e) atomicAdd(&g_deg[dst[i]], 1);
}
// shuffle-based per-block inclusive scan of g_deg -> g_incl; also computes disq
__global__ void scan1(int n) {
    int tid  = threadIdx.x;
    int lane = tid & 31;
    int wid  = tid >> 5;
    int i = blockIdx.x * SCAN_B + tid;
    int d = 0;
    if (i < n) {
        d = g_deg[i];
        g_disq[i] = rsqrtf(1.0f + (float)d);
    }
    int v = d;
#pragma unroll
    for (int o = 1; o < 32; o <<= 1) {
        int t = __shfl_up_sync(0xFFFFFFFFu, v, o);
        if (lane >= o) v += t;
    }
    __shared__ int wsum[32];
    if (lane == 31) wsum[wid] = v;
    __syncthreads();
    if (wid == 0) {
        int w = wsum[lane];
#pragma unroll
        for (int o = 1; o < 32; o <<= 1) {
            int t = __shfl_up_sync(0xFFFFFFFFu, w, o);
            if (lane >= o) w += t;
        }
        wsum[lane] = w;
    }
    __syncthreads();
    int incl = v + ((wid > 0) ? wsum[wid - 1] : 0);
    if (i < n) g_incl[i] = incl;
    if (tid == SCAN_B - 1) g_bsum[blockIdx.x] = incl;
}
// scan3 with scan2 folded in: each block re-scans the <=NB_MAX block sums in smem
__global__ void scan3(int n, int nb) {
    __shared__ int sm[NB_MAX];
    int tid = threadIdx.x;
    if (tid < NB_MAX) sm[tid] = (tid < nb) ? g_bsum[tid] : 0;
    __syncthreads();
#pragma unroll
    for (int off = 1; off < NB_MAX; off <<= 1) {
        int t = (tid < NB_MAX && tid >= off) ? sm[tid - off] : 0;
        __syncthreads();
        if (tid < NB_MAX) sm[tid] += t;
        __syncthreads();
    }
    int i = blockIdx.x * blockDim.x + tid;
    if (i < n) {
        int b = i / SCAN_B;
        int base = (b > 0) ? sm[b - 1] : 0;
        int rs = base + g_incl[i] - g_deg[i];
        g_rowstart[i] = rs;
        g_cursor[i]   = rs;
    }
}
__global__ void fill_csr(const int* __restrict__ src, const int* __restrict__ dst, int e) {
    int i = blockIdx.x * blockDim.x + threadIdx.x;
    if (i < e) {
        int s = src[i], d = dst[i];
        int pos = atomicAdd(&g_cursor[d], 1);
        float w = g_disq[s] * g_disq[d];
        g_csr[pos] = make_int2(s, __float_as_int(w));
    }
}

// ============ fp16 HMMA fragment layout constants ============
#define PA 34
#define FA 136
#define PB 32
#define FB 72
#define XWH (8 * FA)
#define WWH (16 * FB)
#define WWH40 (8 * FB)

// ============ GEMM 128x128, fp16 HMMA m16n8k16, fp32 accum, fp16 out ============
__global__ void __launch_bounds__(256, 2) gemm128_tc(const float* __restrict__ Xf32,
                                                     const float* __restrict__ W,
                                                     const float* __restrict__ stats,
                                                     const float* __restrict__ gam,
                                                     const float* __restrict__ bet,
                                                     int n) {
    __shared__ unsigned Xs[2 * XWH];
    __shared__ unsigned Ws[2 * WWH];
    __shared__ float sc_s[DH];
    __shared__ float sh_s[DH];

    int use_bn = (Xf32 == nullptr);
    int tid  = threadIdx.x;
    int lane = tid & 31;
    int wid  = tid >> 5;
    int warp_m = wid & 1;
    int warp_n = wid >> 1;
    int row0 = blockIdx.x * 128;

    if (use_bn) {
        if (tid < DH) {
            float inv_n = 1.0f / (float)n;
            float mu  = stats[tid] * inv_n;
            float var = stats[DH + tid] * inv_n - mu * mu;
            float rs  = rsqrtf(var + BN_EPS);
            float sc  = rs * gam[tid];
            sc_s[tid] = sc;
            sh_s[tid] = bet[tid] - mu * sc;
        }
        __syncthreads();
    }

    auto load_x4 = [&](int kc, int q) -> float4 {
        int xr = q >> 2, xc4 = q & 3;
        int gr = row0 + xr;
        float4 v = make_float4(0.f, 0.f, 0.f, 0.f);
        if (use_bn) {
            if (gr < n) {
                uint2 u = *(const uint2*)(g_h16 + (size_t)gr * DH + kc * 16 + xc4 * 4);
                h2x2_to_f4(u, v);
            }
            float4 sc = *(const float4*)(sc_s + kc * 16 + xc4 * 4);
            float4 sh = *(const float4*)(sh_s + kc * 16 + xc4 * 4);
            v.x = fmaxf(0.f, fmaf(v.x, sc.x, sh.x));
            v.y = fmaxf(0.f, fmaf(v.y, sc.y, sh.y));
            v.z = fmaxf(0.f, fmaf(v.z, sc.z, sh.z));
            v.w = fmaxf(0.f, fmaf(v.w, sc.w, sh.w));
        } else {
            if (gr < n) v = *(const float4*)(Xf32 + (size_t)gr * DH + kc * 16 + xc4 * 4);
        }
        return v;
    };
    auto store_x4 = [&](float4 v, int q, int buf) {
        int xr = q >> 2, xc4 = q & 3;
        int tm = xr >> 4, ri = xr & 15;
        int rh = ri >> 3, gg = ri & 7;
        int kh = xc4 >> 1;
        int j  = rh + 2 * kh;
        int tg0 = (xc4 & 1) * 2;
        int base = buf * XWH + tm * FA + j * PA + gg * 4 + tg0;
        uint2 w;
        w.x = h2u(v.x, v.y);
        w.y = h2u(v.z, v.w);
        *(uint2*)&Xs[base] = w;
    };
    auto store_w = [&](int kc, int q, int buf) {
        int kp = q >> 6;
        int n0 = (q & 63) * 2;
        int k0 = kc * 16 + kp * 2;
        float2 r0 = *(const float2*)(W + (size_t)k0 * DH + n0);
        float2 r1 = *(const float2*)(W + (size_t)(k0 + 1) * DH + n0);
        int nt = n0 >> 3, g = n0 & 7;
        int j  = kp >> 2, tg = kp & 3;
        int base = buf * WWH + nt * FB + j * PB + tg * 8 + g;
        uint2 w;
        w.x = h2u(r0.x, r1.x);
        w.y = h2u(r0.y, r1.y);
        *(uint2*)&Ws[base] = w;
    };

    float acc[4][4][4];
#pragma unroll
    for (int mt = 0; mt < 4; mt++)
#pragma unroll
        for (int nt = 0; nt < 4; nt++)
#pragma unroll
            for (int k = 0; k < 4; k++) acc[mt][nt][k] = 0.f;

    int wb_off = (lane & 3) * 8 + (lane >> 2);

    store_x4(load_x4(0, tid), tid, 0);
    store_x4(load_x4(0, tid + 256), tid + 256, 0);
    store_w(0, tid, 0);
    store_w(0, tid + 256, 0);
    __syncthreads();

    int buf = 0;
    for (int kc = 0; kc < 8; kc++) {
        float4 px0, px1;
        if (kc < 7) {
            px0 = load_x4(kc + 1, tid);
            px1 = load_x4(kc + 1, tid + 256);
        }

        unsigned bfr[4][2];
#pragma unroll
        for (int nt = 0; nt < 4; nt++) {
            int f = buf * WWH + (warp_n * 4 + nt) * FB + wb_off;
            bfr[nt][0] = Ws[f];
            bfr[nt][1] = Ws[f + PB];
        }
#pragma unroll
        for (int mt = 0; mt < 4; mt++) {
            int f = buf * XWH + (warp_m * 4 + mt) * FA + lane;
            unsigned afr[4];
#pragma unroll
            for (int jj = 0; jj < 4; jj++) afr[jj] = Xs[f + jj * PA];
#pragma unroll
            for (int nt = 0; nt < 4; nt++)
                mma_f16(acc[mt][nt], afr, bfr[nt]);
        }

        if (kc < 7) {
            store_x4(px0, tid, buf ^ 1);
            store_x4(px1, tid + 256, buf ^ 1);
            store_w(kc + 1, tid, buf ^ 1);
            store_w(kc + 1, tid + 256, buf ^ 1);
        }
        __syncthreads();
        buf ^= 1;
    }

    int g  = lane >> 2;
    int tg = lane & 3;
#pragma unroll
    for (int mt = 0; mt < 4; mt++)
#pragma unroll
        for (int nt = 0; nt < 4; nt++) {
            int r = row0 + warp_m * 64 + mt * 16 + g;
            int c = warp_n * 32 + nt * 8 + tg * 2;
            if (r < n)
                *(__half2*)(g_t16 + (size_t)r * DH + c) =
                    __float22half2_rn(make_float2(acc[mt][nt][0], acc[mt][nt][1]));
            if (r + 8 < n)
                *(__half2*)(g_t16 + (size_t)(r + 8) * DH + c) =
                    __float22half2_rn(make_float2(acc[mt][nt][2], acc[mt][nt][3]));
        }
}

// ============ GEMM 128x64 (N=40 zero-padded), fp16 HMMA, BN in prologue ============
__global__ void __launch_bounds__(256, 2) gemm40_tc(const float* __restrict__ W2,
                                                    const float* __restrict__ stats,
                                                    const float* __restrict__ gam,
                                                    const float* __restrict__ bet,
                                                    int n) {
    __shared__ unsigned Xs[2 * XWH];
    __shared__ unsigned Ws[2 * WWH40];
    __shared__ float sc_s[DH];
    __shared__ float sh_s[DH];

    int tid  = threadIdx.x;
    int lane = tid & 31;
    int wid  = tid >> 5;
    int warp_m = wid & 1;
    int warp_n = wid >> 1;
    int row0 = blockIdx.x * 128;

    if (tid < DH) {
        float inv_n = 1.0f / (float)n;
        float mu  = stats[tid] * inv_n;
        float var = stats[DH + tid] * inv_n - mu * mu;
        float rs  = rsqrtf(var + BN_EPS);
        float sc  = rs * gam[tid];
        sc_s[tid] = sc;
        sh_s[tid] = bet[tid] - mu * sc;
    }
    __syncthreads();

    auto load_x4 = [&](int kc, int q) -> float4 {
        int xr = q >> 2, xc4 = q & 3;
        int gr = row0 + xr;
        float4 v = make_float4(0.f, 0.f, 0.f, 0.f);
        if (gr < n) {
            uint2 u = *(const uint2*)(g_h16 + (size_t)gr * DH + kc * 16 + xc4 * 4);
            h2x2_to_f4(u, v);
        }
        float4 sc = *(const float4*)(sc_s + kc * 16 + xc4 * 4);
        float4 sh = *(const float4*)(sh_s + kc * 16 + xc4 * 4);
        v.x = fmaxf(0.f, fmaf(v.x, sc.x, sh.x));
        v.y = fmaxf(0.f, fmaf(v.y, sc.y, sh.y));
        v.z = fmaxf(0.f, fmaf(v.z, sc.z, sh.z));
        v.w = fmaxf(0.f, fmaf(v.w, sc.w, sh.w));
        return v;
    };
    auto store_x4 = [&](float4 v, int q, int buf) {
        int xr = q >> 2, xc4 = q & 3;
        int tm = xr >> 4, ri = xr & 15;
        int rh = ri >> 3, gg = ri & 7;
        int kh = xc4 >> 1;
        int j  = rh + 2 * kh;
        int tg0 = (xc4 & 1) * 2;
        int base = buf * XWH + tm * FA + j * PA + gg * 4 + tg0;
        uint2 w;
        w.x = h2u(v.x, v.y);
        w.y = h2u(v.z, v.w);
        *(uint2*)&Xs[base] = w;
    };
    auto store_w = [&](int kc, int q, int buf) {
        int kp = q >> 5;
        int n0 = (q & 31) * 2;
        int k0 = kc * 16 + kp * 2;
        float a0 = 0.f, a1 = 0.f, b0 = 0.f, b1 = 0.f;
        if (n0 < DOUT)     { a0 = W2[(size_t)k0 * DOUT + n0];
                             b0 = W2[(size_t)(k0 + 1) * DOUT + n0]; }
        if (n0 + 1 < DOUT) { a1 = W2[(size_t)k0 * DOUT + n0 + 1];
                             b1 = W2[(size_t)(k0 + 1) * DOUT + n0 + 1]; }
        int nt = n0 >> 3, g = n0 & 7;
        int j  = kp >> 2, tg = kp & 3;
        int base = buf * WWH40 + nt * FB + j * PB + tg * 8 + g;
        uint2 w;
        w.x = h2u(a0, b0);
        w.y = h2u(a1, b1);
        *(uint2*)&Ws[base] = w;
    };

    float acc[4][2][4];
#pragma unroll
    for (int mt = 0; mt < 4; mt++)
#pragma unroll
        for (int nt = 0; nt < 2; nt++)
#pragma unroll
            for (int k = 0; k < 4; k++) acc[mt][nt][k] = 0.f;

    int wb_off = (lane & 3) * 8 + (lane >> 2);

    store_x4(load_x4(0, tid), tid, 0);
    store_x4(load_x4(0, tid + 256), tid + 256, 0);
    store_w(0, tid, 0);
    __syncthreads();

    int buf = 0;
    for (int kc = 0; kc < 8; kc++) {
        float4 px0, px1;
        if (kc < 7) {
            px0 = load_x4(kc + 1, tid);
            px1 = load_x4(kc + 1, tid + 256);
        }

        unsigned bfr[2][2];
#pragma unroll
        for (int nt = 0; nt < 2; nt++) {
            int f = buf * WWH40 + (warp_n * 2 + nt) * FB + wb_off;
            bfr[nt][0] = Ws[f];
            bfr[nt][1] = Ws[f + PB];
        }
#pragma unroll
        for (int mt = 0; mt < 4; mt++) {
            int f = buf * XWH + (warp_m * 4 + mt) * FA + lane;
            unsigned afr[4];
#pragma unroll
            for (int jj = 0; jj < 4; jj++) afr[jj] = Xs[f + jj * PA];
#pragma unroll
            for (int nt = 0; nt < 2; nt++)
                mma_f16(acc[mt][nt], afr, bfr[nt]);
        }

        if (kc < 7) {
            store_x4(px0, tid, buf ^ 1);
            store_x4(px1, tid + 256, buf ^ 1);
            store_w(kc + 1, tid, buf ^ 1);
        }
        __syncthreads();
        buf ^= 1;
    }

    int g  = lane >> 2;
    int tg = lane & 3;
#pragma unroll
    for (int mt = 0; mt < 4; mt++)
#pragma unroll
        for (int nt = 0; nt < 2; nt++) {
            int r = row0 + warp_m * 64 + mt * 16 + g;
            int c = warp_n * 16 + nt * 8 + tg * 2;
            if (r < n)
                *(__half2*)(g_t40 + (size_t)r * DOUTP + c) =
                    __float22half2_rn(make_float2(acc[mt][nt][0], acc[mt][nt][1]));
            if (r + 8 < n)
                *(__half2*)(g_t40 + (size_t)(r + 8) * DOUTP + c) =
                    __float22half2_rn(make_float2(acc[mt][nt][2], acc[mt][nt][3]));
        }
}

// ---------------- fused aggregate + combine + BN stats, F=128 (fp16 gather, 8x/4x unroll) ----------------
__global__ void __launch_bounds__(256) agg_combine128(const float* __restrict__ b,
                                                      float* __restrict__ stats, int n) {
    int lane = threadIdx.x & 31;
    int wip  = threadIdx.x >> 5;
    float4 bc = ((const float4*)b)[lane];

    float4 ssum = make_float4(0.f, 0.f, 0.f, 0.f);
    float4 ssq  = make_float4(0.f, 0.f, 0.f, 0.f);

    for (int row = blockIdx.x * 8 + wip; row < n; row += gridDim.x * 8) {
        int start = g_rowstart[row];
        int jend  = start + g_deg[row];
        float4 acc = make_float4(0.f, 0.f, 0.f, 0.f);
        int j = start;
        for (; j + 8 <= jend; j += 8) {
            int2 p[8];
            uint2 u[8];
#pragma unroll
            for (int q = 0; q < 8; q++) p[q] = g_csr[j + q];
#pragma unroll
            for (int q = 0; q < 8; q++)
                u[q] = __ldg((const uint2*)(g_t16 + (size_t)p[q].x * DH) + lane);
#pragma unroll
            for (int q = 0; q < 8; q++) {
                float4 v; h2x2_to_f4(u[q], v);
                float w = __int_as_float(p[q].y);
                acc.x = fmaf(w, v.x, acc.x); acc.y = fmaf(w, v.y, acc.y);
                acc.z = fmaf(w, v.z, acc.z); acc.w = fmaf(w, v.w, acc.w);
            }
        }
        for (; j + 4 <= jend; j += 4) {
            int2 p0 = g_csr[j],     p1 = g_csr[j + 1];
            int2 p2 = g_csr[j + 2], p3 = g_csr[j + 3];
            uint2 u0 = __ldg((const uint2*)(g_t16 + (size_t)p0.x * DH) + lane);
            uint2 u1 = __ldg((const uint2*)(g_t16 + (size_t)p1.x * DH) + lane);
            uint2 u2 = __ldg((const uint2*)(g_t16 + (size_t)p2.x * DH) + lane);
            uint2 u3 = __ldg((const uint2*)(g_t16 + (size_t)p3.x * DH) + lane);
            float4 v0, v1, v2, v3;
            h2x2_to_f4(u0, v0); h2x2_to_f4(u1, v1);
            h2x2_to_f4(u2, v2); h2x2_to_f4(u3, v3);
            float w0 = __int_as_float(p0.y), w1 = __int_as_float(p1.y);
            float w2 = __int_as_float(p2.y), w3 = __int_as_float(p3.y);
            acc.x = fmaf(w0, v0.x, acc.x); acc.y = fmaf(w0, v0.y, acc.y);
            acc.z = fmaf(w0, v0.z, acc.z); acc.w = fmaf(w0, v0.w, acc.w);
            acc.x = fmaf(w1, v1.x, acc.x); acc.y = fmaf(w1, v1.y, acc.y);
            acc.z = fmaf(w1, v1.z, acc.z); acc.w = fmaf(w1, v1.w, acc.w);
            acc.x = fmaf(w2, v2.x, acc.x); acc.y = fmaf(w2, v2.y, acc.y);
            acc.z = fmaf(w2, v2.z, acc.z); acc.w = fmaf(w2, v2.w, acc.w);
            acc.x = fmaf(w3, v3.x, acc.x); acc.y = fmaf(w3, v3.y, acc.y);
            acc.z = fmaf(w3, v3.z, acc.z); acc.w = fmaf(w3, v3.w, acc.w);
        }
        for (; j < jend; j++) {
            int2 pr = g_csr[j];
            float w = __int_as_float(pr.y);
            uint2 u = __ldg((const uint2*)(g_t16 + (size_t)pr.x * DH) + lane);
            float4 v; h2x2_to_f4(u, v);
            acc.x = fmaf(w, v.x, acc.x); acc.y = fmaf(w, v.y, acc.y);
            acc.z = fmaf(w, v.z, acc.z); acc.w = fmaf(w, v.w, acc.w);
        }
        float dq = g_disq[row];
        float sn = dq * dq;
        uint2 us = __ldg((const uint2*)(g_t16 + (size_t)row * DH) + lane);
        float4 t; h2x2_to_f4(us, t);
        float4 h;
        h.x = fmaf(sn, t.x, acc.x) + bc.x;
        h.y = fmaf(sn, t.y, acc.y) + bc.y;
        h.z = fmaf(sn, t.z, acc.z) + bc.z;
        h.w = fmaf(sn, t.w, acc.w) + bc.w;
        *((uint2*)(g_h16 + (size_t)row * DH) + lane) = f4_to_h2x2(h);
        ssum.x += h.x; ssum.y += h.y; ssum.z += h.z; ssum.w += h.w;
        ssq.x = fmaf(h.x, h.x, ssq.x); ssq.y = fmaf(h.y, h.y, ssq.y);
        ssq.z = fmaf(h.z, h.z, ssq.z); ssq.w = fmaf(h.w, h.w, ssq.w);
    }

    __shared__ float4 sh1[8][32];
    __shared__ float4 sh2[8][32];
    sh1[wip][lane] = ssum;
    sh2[wip][lane] = ssq;
    __syncthreads();
    if (wip == 0) {
        float4 a = sh1[0][lane], q = sh2[0][lane];
#pragma unroll
        for (int w = 1; w < 8; w++) {
            float4 a2 = sh1[w][lane], q2 = sh2[w][lane];
            a.x += a2.x; a.y += a2.y; a.z += a2.z; a.w += a2.w;
            q.x += q2.x; q.y += q2.y; q.z += q2.z; q.w += q2.w;
        }
        red_add_v4(stats + lane * 4, a);
        red_add_v4(stats + DH + lane * 4, q);
    }
}

// ---------------- fused aggregate + combine + log_softmax, F=40 (padded 64, 4x unroll) ----------------
__global__ void __launch_bounds__(256) agg40_lsm(const float* __restrict__ b2,
                                                 float* __restrict__ out, int n) {
    int lane = threadIdx.x & 31;
    int wip  = threadIdx.x >> 5;
    bool active = (lane < 10);
    float4 bc = make_float4(0.f, 0.f, 0.f, 0.f);
    if (active) bc = ((const float4*)b2)[lane];

    for (int row = blockIdx.x * 8 + wip; row < n; row += gridDim.x * 8) {
        int start = g_rowstart[row];
        int jend  = start + g_deg[row];
        float4 acc = make_float4(0.f, 0.f, 0.f, 0.f);
        int j = start;
        for (; j + 4 <= jend; j += 4) {
            int2 p0 = g_csr[j],     p1 = g_csr[j + 1];
            int2 p2 = g_csr[j + 2], p3 = g_csr[j + 3];
            if (active) {
                uint2 u0 = __ldg((const uint2*)(g_t40 + (size_t)p0.x * DOUTP) + lane);
                uint2 u1 = __ldg((const uint2*)(g_t40 + (size_t)p1.x * DOUTP) + lane);
                uint2 u2 = __ldg((const uint2*)(g_t40 + (size_t)p2.x * DOUTP) + lane);
                uint2 u3 = __ldg((const uint2*)(g_t40 + (size_t)p3.x * DOUTP) + lane);
                float4 v0, v1, v2, v3;
                h2x2_to_f4(u0, v0); h2x2_to_f4(u1, v1);
                h2x2_to_f4(u2, v2); h2x2_to_f4(u3, v3);
                float w0 = __int_as_float(p0.y), w1 = __int_as_float(p1.y);
                float w2 = __int_as_float(p2.y), w3 = __int_as_float(p3.y);
                acc.x = fmaf(w0, v0.x, acc.x); acc.y = fmaf(w0, v0.y, acc.y);
                acc.z = fmaf(w0, v0.z, acc.z); acc.w = fmaf(w0, v0.w, acc.w);
                acc.x = fmaf(w1, v1.x, acc.x); acc.y = fmaf(w1, v1.y, acc.y);
                acc.z = fmaf(w1, v1.z, acc.z); acc.w = fmaf(w1, v1.w, acc.w);
                acc.x = fmaf(w2, v2.x, acc.x); acc.y = fmaf(w2, v2.y, acc.y);
                acc.z = fmaf(w2, v2.z, acc.z); acc.w = fmaf(w2, v2.w, acc.w);
                acc.x = fmaf(w3, v3.x, acc.x); acc.y = fmaf(w3, v3.y, acc.y);
                acc.z = fmaf(w3, v3.z, acc.z); acc.w = fmaf(w3, v3.w, acc.w);
            }
        }
        for (; j < jend; j++) {
            int2 pr = g_csr[j];
            if (active) {
                float w = __int_as_float(pr.y);
                uint2 u = __ldg((const uint2*)(g_t40 + (size_t)pr.x * DOUTP) + lane);
                float4 v; h2x2_to_f4(u, v);
                acc.x = fmaf(w, v.x, acc.x); acc.y = fmaf(w, v.y, acc.y);
                acc.z = fmaf(w, v.z, acc.z); acc.w = fmaf(w, v.w, acc.w);
            }
        }
        float dq = g_disq[row];
        float sn = dq * dq;
        float4 h = make_float4(-1e30f, -1e30f, -1e30f, -1e30f);
        if (active) {
            uint2 us = __ldg((const uint2*)(g_t40 + (size_t)row * DOUTP) + lane);
            float4 t; h2x2_to_f4(us, t);
            h.x = fmaf(sn, t.x, acc.x) + bc.x;
            h.y = fmaf(sn, t.y, acc.y) + bc.y;
            h.z = fmaf(sn, t.z, acc.z) + bc.z;
            h.w = fmaf(sn, t.w, acc.w) + bc.w;
        }
        float m = fmaxf(fmaxf(h.x, h.y), fmaxf(h.z, h.w));
#pragma unroll
        for (int o = 16; o; o >>= 1) m = fmaxf(m, __shfl_xor_sync(0xFFFFFFFFu, m, o));
        float se = 0.f;
        if (active)
            se = expf(h.x - m) + expf(h.y - m) + expf(h.z - m) + expf(h.w - m);
#pragma unroll
        for (int o = 16; o; o >>= 1) se += __shfl_xor_sync(0xFFFFFFFFu, se, o);
        float lse = m + logf(se);
        if (active) {
            float4 r = make_float4(h.x - lse, h.y - lse, h.z - lse, h.w - lse);
            ((float4*)out)[(size_t)row * 10 + lane] = r;
        }
    }
}

// ---------------- launch ----------------
extern "C" void kernel_launch(void* const* d_in, const int* in_sizes, int n_in,
                              void* d_out, int out_size) {
    const float* x   = (const float*)d_in[0];
    const int*   src = (const int*)d_in[1];
    const int*   dst = (const int*)d_in[2];
    const float* W0  = (const float*)d_in[3];
    const float* b0  = (const float*)d_in[4];
    const float* W1  = (const float*)d_in[5];
    const float* b1  = (const float*)d_in[6];
    const float* W2  = (const float*)d_in[7];
    const float* b2  = (const float*)d_in[8];
    const float* g0  = (const float*)d_in[9];
    const float* be0 = (const float*)d_in[10];
    const float* g1  = (const float*)d_in[11];
    const float* be1 = (const float*)d_in[12];
    float* out = (float*)d_out;

    int n = in_sizes[0] / DH;
    int e = in_sizes[1];
    int nb = (n + SCAN_B - 1) / SCAN_B;

    int agg_blocks  = 1184;   // 148 SMs x 8 CTAs -> exactly one wave (64 warps/SM)
    int gemm_blocks = (n + 127) / 128;

    float* stats0_p; cudaGetSymbolAddress((void**)&stats0_p, g_stats0);
    float* stats1_p; cudaGetSymbolAddress((void**)&stats1_p, g_stats1);

    // ---- fork: CSR chain on g_s2 concurrent with layer-0 GEMM on main ----
    cudaEventRecord(g_ev_fork, 0);
    cudaStreamWaitEvent(g_s2, g_ev_fork, 0);

    gemm128_tc<<<gemm_blocks, 256>>>(x, W0, nullptr, nullptr, nullptr, n);

    zero_misc<<<(n + 255) / 256, 256, 0, g_s2>>>(n);
    count_deg<<<(e + 255) / 256, 256, 0, g_s2>>>(dst, e);
    scan1<<<nb, SCAN_B, 0, g_s2>>>(n);
    scan3<<<(n + 255) / 256, 256, 0, g_s2>>>(n, nb);   // scan2 folded in
    fill_csr<<<(e + 255) / 256, 256, 0, g_s2>>>(src, dst, e);

    cudaEventRecord(g_ev_join, g_s2);
    cudaStreamWaitEvent(0, g_ev_join, 0);

    // ---- layer 0 agg ----
    agg_combine128<<<agg_blocks, 256>>>(b0, stats0_p, n);

    // ---- layer 1 ----
    gemm128_tc<<<gemm_blocks, 256>>>(nullptr, W1, stats0_p, g0, be0, n);
    agg_combine128<<<agg_blocks, 256>>>(b1, stats1_p, n);

    // ---- layer 2 ----
    gemm40_tc<<<gemm_blocks, 256>>>(W2, stats1_p, g1, be1, n);
    agg40_lsm<<<agg_blocks, 256>>>(b2, out, n);
}